// round 8
// baseline (speedup 1.0000x reference)
#include <cuda_runtime.h>
#include <cuda_fp16.h>
#include <cstdint>

#define B_    1024
#define T_    512
#define OBS_  64
#define H_    256
#define A_    16
#define NCOL  8               // batch columns per CTA
#define NBLK  (B_ / NCOL)     // 128 CTAs
#define NTH   288             // 8 compute warps (2 m16-tiles each) + 1 output warp
#define XBUF  5120            // bytes per x buffer ([h;obs] x 8 cols fp16)

__device__ __forceinline__ float sigm(float x) {           // accurate: EX2 + RCP
    float e, r;
    asm("ex2.approx.f32 %0, %1;" : "=f"(e) : "f"(-1.4426950408889634f * x));
    asm("rcp.approx.f32 %0, %1;" : "=f"(r) : "f"(1.0f + e));
    return r;
}
__device__ __forceinline__ float tanh_(float x) {          // fast path for h
    float t;
    asm("tanh.approx.f32 %0, %1;" : "=f"(t) : "f"(x));
    return t;
}
__device__ __forceinline__ uint32_t f2h2(float x, float y) {
    __half2 h = __floats2half2_rn(x, y);
    return *(uint32_t*)&h;
}
__device__ __forceinline__ void sts16(uint32_t a, float v) {
    uint16_t u = __half_as_ushort(__float2half_rn(v));
    asm volatile("st.shared.u16 [%0], %1;" :: "r"(a), "h"(u) : "memory");
}
__device__ __forceinline__ void ldfrag(uint32_t* f, const float* p0, const float* p1) {
    float2 a = *(const float2*)p0,       b = *(const float2*)p1;
    float2 c = *(const float2*)(p0 + 8), d = *(const float2*)(p1 + 8);
    f[0] = f2h2(a.x, a.y); f[1] = f2h2(b.x, b.y);
    f[2] = f2h2(c.x, c.y); f[3] = f2h2(d.x, d.y);
}
#define MMA(d0,d1,d2,d3,a,b0,b1) \
    asm("mma.sync.aligned.m16n8k16.row.col.f32.f16.f16.f32 " \
        "{%0,%1,%2,%3},{%4,%5,%6,%7},{%8,%9},{%0,%1,%2,%3};" \
        : "+f"(d0), "+f"(d1), "+f"(d2), "+f"(d3) \
        : "r"((a)[0]), "r"((a)[1]), "r"((a)[2]), "r"((a)[3]), "r"(b0), "r"(b1))
#define LDSV2(b0,b1,addr) \
    asm volatile("ld.shared.v2.b32 {%0,%1}, [%2];" : "=r"(b0), "=r"(b1) : "r"(addr))

// x layout per buffer (u32 words): word(k,n) = ((k>>4)*4 + ((k&7)>>1))*16 + 2n + ((k>>3)&1),
// halfword k&1.  B-frag of thread (tig,gid) for chunk kc = ONE ld.shared.v2.b32
// at xbase + (tig*8+gid)*8 + kc*256.
__global__ void __launch_bounds__(NTH, 1)
rnn_hmma3_kernel(const float* __restrict__ obs,   const float* __restrict__ W_in,
                 const float* __restrict__ W_h,   const float* __restrict__ b_h,
                 const float* __restrict__ W_out, const float* __restrict__ b_out,
                 float* __restrict__ out)
{
    __shared__ __align__(16) uint32_t xS[2 * 1280];

    const int tid  = threadIdx.x;
    const int wid  = tid >> 5;
    const int gid  = (tid & 31) >> 2;
    const int tig  = tid & 3;
    const int kq   = tig * 2;
    const int row0 = blockIdx.x * NCOL;
    const uint32_t xbase = (uint32_t)__cvta_generic_to_shared(xS);
    const uint32_t baddr = xbase + (uint32_t)((tig * 8 + gid) * 8);

    float* out_h = out + (size_t)B_ * T_ * A_;
    float* out_o = out_h + (size_t)B_ * H_;

    // ---- init: zero both x buffers ----
    for (int i = tid; i < 2560; i += NTH) xS[i] = 0u;
    __syncthreads();

    // obs staging identity (threads 0..255: rows n_ob and n_ob+4, element kk)
    const int n_ob = tid >> 6, kk = tid & 63;
    const uint32_t obA = xbase + (uint32_t)((16 + (kk >> 4)) * 256 + ((kk & 7) >> 1) * 64 +
                                            n_ob * 8 + ((kk >> 3) & 1) * 4 + (kk & 1) * 2);
    const float* op = obs + (size_t)(row0 + n_ob) * T_ * OBS_ + kk;
    const size_t OSTR = (size_t)4 * T_ * OBS_;          // +4 batch rows

    // obs(0) -> buf0 directly; obs(1) -> registers (depth-2 pipeline)
    float p0 = 0.f, p1 = 0.f;
    if (tid < 256) {
        sts16(obA, op[0]); sts16(obA + 32, op[OSTR]);
        p0 = op[OBS_]; p1 = op[OBS_ + OSTR];            // t = 1
    }

    if (wid < 8) {
        // ================= compute warps: 2 m16-tiles of pre_h =================
        const int rbase = wid * 32;
        uint32_t af[2][20][4];
        #pragma unroll
        for (int m = 0; m < 2; m++) {
            const int rA = rbase + m * 16 + gid;
            #pragma unroll
            for (int kc = 0; kc < 16; kc++)
                ldfrag(af[m][kc], W_h + rA * H_ + kc * 16 + kq,
                                  W_h + (rA + 8) * H_ + kc * 16 + kq);
            #pragma unroll
            for (int kc = 16; kc < 20; kc++)
                ldfrag(af[m][kc], W_in + rA * OBS_ + (kc - 16) * 16 + kq,
                                  W_in + (rA + 8) * OBS_ + (kc - 16) * 16 + kq);
        }
        const float bh0 = b_h[rbase + gid],      bh1 = b_h[rbase + gid + 8];
        const float bh2 = b_h[rbase + gid + 16], bh3 = b_h[rbase + gid + 24];

        // h write-back base: row rbase+gid, col 2*tig; offsets {0,8,4,12,256,264,260,268}
        const uint32_t hA = xbase +
            (uint32_t)(4 * (((((rbase >> 4) << 2) | (gid >> 1)) << 4) + 4 * tig) + (gid & 1) * 2);

        float s00 = 0.f, s01 = 0.f, s02 = 0.f, s03 = 0.f;
        float s10 = 0.f, s11 = 0.f, s12 = 0.f, s13 = 0.f;

        for (int t = 0; t < T_; t++) {
            __syncthreads();                               // x[t&1] ready
            // depth-2 prefetch: load obs(t+2) now; store obs(t+1) (loaded last step)
            float np0 = 0.f, np1 = 0.f;
            if (tid < 256 && t + 2 < T_) {
                np0 = op[(size_t)(t + 2) * OBS_];
                np1 = op[(size_t)(t + 2) * OBS_ + OSTR];
            }
            const uint32_t xb = baddr + (uint32_t)((t & 1) * XBUF);

            // 4-way accumulator split per tile: chains of 5 HMMA
            float A0 = bh0, A1 = bh0, A2 = bh1, A3 = bh1;       // tile0 kc%4==0
            float B0 = 0.f, B1 = 0.f, B2 = 0.f, B3 = 0.f;       // tile0 kc%4==1
            float C0 = 0.f, C1 = 0.f, C2 = 0.f, C3 = 0.f;       // tile0 kc%4==2
            float D0 = 0.f, D1 = 0.f, D2 = 0.f, D3 = 0.f;       // tile0 kc%4==3
            float E0 = bh2, E1 = bh2, E2 = bh3, E3 = bh3;       // tile1 kc%4==0
            float F0 = 0.f, F1 = 0.f, F2 = 0.f, F3 = 0.f;
            float G0 = 0.f, G1 = 0.f, G2 = 0.f, G3 = 0.f;
            float H0 = 0.f, H1 = 0.f, H2 = 0.f, H3 = 0.f;
            #pragma unroll
            for (int kc = 0; kc < 20; kc += 4) {
                uint32_t b0, b1, c0, c1, d0, d1, e0, e1;
                LDSV2(b0, b1, xb + kc * 256);
                LDSV2(c0, c1, xb + (kc + 1) * 256);
                LDSV2(d0, d1, xb + (kc + 2) * 256);
                LDSV2(e0, e1, xb + (kc + 3) * 256);
                MMA(A0, A1, A2, A3, af[0][kc],     b0, b1);
                MMA(E0, E1, E2, E3, af[1][kc],     b0, b1);
                MMA(B0, B1, B2, B3, af[0][kc + 1], c0, c1);
                MMA(F0, F1, F2, F3, af[1][kc + 1], c0, c1);
                MMA(C0, C1, C2, C3, af[0][kc + 2], d0, d1);
                MMA(G0, G1, G2, G3, af[1][kc + 2], d0, d1);
                MMA(D0, D1, D2, D3, af[0][kc + 3], e0, e1);
                MMA(H0, H1, H2, H3, af[1][kc + 3], e0, e1);
            }
            s00 = fmaf(0.9f, s00, fmaf(0.05f, tanh_(0.5f * ((A0 + B0) + (C0 + D0))), 0.05f));
            s01 = fmaf(0.9f, s01, fmaf(0.05f, tanh_(0.5f * ((A1 + B1) + (C1 + D1))), 0.05f));
            s02 = fmaf(0.9f, s02, fmaf(0.05f, tanh_(0.5f * ((A2 + B2) + (C2 + D2))), 0.05f));
            s03 = fmaf(0.9f, s03, fmaf(0.05f, tanh_(0.5f * ((A3 + B3) + (C3 + D3))), 0.05f));
            s10 = fmaf(0.9f, s10, fmaf(0.05f, tanh_(0.5f * ((E0 + F0) + (G0 + H0))), 0.05f));
            s11 = fmaf(0.9f, s11, fmaf(0.05f, tanh_(0.5f * ((E1 + F1) + (G1 + H1))), 0.05f));
            s12 = fmaf(0.9f, s12, fmaf(0.05f, tanh_(0.5f * ((E2 + F2) + (G2 + H2))), 0.05f));
            s13 = fmaf(0.9f, s13, fmaf(0.05f, tanh_(0.5f * ((E3 + F3) + (G3 + H3))), 0.05f));

            const uint32_t hw = hA + (uint32_t)(((t + 1) & 1) * XBUF);
            sts16(hw,       s00); sts16(hw + 8,   s01);
            sts16(hw + 4,   s02); sts16(hw + 12,  s03);
            sts16(hw + 256, s10); sts16(hw + 264, s11);
            sts16(hw + 260, s12); sts16(hw + 268, s13);
            if (tid < 256) {
                const uint32_t ow = obA + (uint32_t)(((t + 1) & 1) * XBUF);
                sts16(ow, p0); sts16(ow + 32, p1);     // obs(t+1), loaded a step ago
                p0 = np0; p1 = np1;
            }
        }
        __syncthreads();

        // final h states: rows {rbase+gid,+8,+16,+24}, cols {2tig, 2tig+1}
        const int c0 = tig * 2, j0 = rbase + gid;
        out_h[(size_t)(row0 + c0)     * H_ + j0]      = s00;
        out_h[(size_t)(row0 + c0 + 1) * H_ + j0]      = s01;
        out_h[(size_t)(row0 + c0)     * H_ + j0 + 8]  = s02;
        out_h[(size_t)(row0 + c0 + 1) * H_ + j0 + 8]  = s03;
        out_h[(size_t)(row0 + c0)     * H_ + j0 + 16] = s10;
        out_h[(size_t)(row0 + c0 + 1) * H_ + j0 + 16] = s11;
        out_h[(size_t)(row0 + c0)     * H_ + j0 + 24] = s12;
        out_h[(size_t)(row0 + c0 + 1) * H_ + j0 + 24] = s13;
    } else {
        // ================= output warp: pre_o = W_out @ h (one step behind) =================
        uint32_t afo[16][4];
        #pragma unroll
        for (int kc = 0; kc < 16; kc++)
            ldfrag(afo[kc], W_out + gid * H_ + kc * 16 + kq,
                            W_out + (gid + 8) * H_ + kc * 16 + kq);
        const float bo0 = b_out[gid], bo1 = b_out[gid + 8];
        float s0 = 0.f, s1 = 0.f, s2 = 0.f, s3 = 0.f;
        const int c0 = tig * 2;

        for (int t = 0; t < T_; t++) {
            __syncthreads();
            if (t > 0) {
                const uint32_t xb = baddr + (uint32_t)((t & 1) * XBUF);
                float E0 = bo0, E1 = bo0, E2 = bo1, E3 = bo1;
                float O0 = 0.f, O1 = 0.f, O2 = 0.f, O3 = 0.f;
                #pragma unroll
                for (int kc = 0; kc < 16; kc += 2) {
                    uint32_t b0, b1, c1, c2;
                    LDSV2(b0, b1, xb + kc * 256);
                    LDSV2(c1, c2, xb + (kc + 1) * 256);
                    MMA(E0, E1, E2, E3, afo[kc], b0, b1);
                    MMA(O0, O1, O2, O3, afo[kc + 1], c1, c2);
                }
                s0 = fmaf(0.9f, s0, 0.1f * sigm(E0 + O0));
                s1 = fmaf(0.9f, s1, 0.1f * sigm(E1 + O1));
                s2 = fmaf(0.9f, s2, 0.1f * sigm(E2 + O2));
                s3 = fmaf(0.9f, s3, 0.1f * sigm(E3 + O3));
                size_t o0i = ((size_t)(row0 + c0)     * T_ + (t - 1)) * A_ + gid;
                size_t o1i = ((size_t)(row0 + c0 + 1) * T_ + (t - 1)) * A_ + gid;
                out[o0i] = s0; out[o1i] = s1; out[o0i + 8] = s2; out[o1i + 8] = s3;
            }
        }
        __syncthreads();

        // final pass: consume h_{T-1} from buf[T&1]==buf0
        {
            const uint32_t xb = baddr;
            float E0 = bo0, E1 = bo0, E2 = bo1, E3 = bo1;
            float O0 = 0.f, O1 = 0.f, O2 = 0.f, O3 = 0.f;
            #pragma unroll
            for (int kc = 0; kc < 16; kc += 2) {
                uint32_t b0, b1, c1, c2;
                LDSV2(b0, b1, xb + kc * 256);
                LDSV2(c1, c2, xb + (kc + 1) * 256);
                MMA(E0, E1, E2, E3, afo[kc], b0, b1);
                MMA(O0, O1, O2, O3, afo[kc + 1], c1, c2);
            }
            s0 = fmaf(0.9f, s0, 0.1f * sigm(E0 + O0));
            s1 = fmaf(0.9f, s1, 0.1f * sigm(E1 + O1));
            s2 = fmaf(0.9f, s2, 0.1f * sigm(E2 + O2));
            s3 = fmaf(0.9f, s3, 0.1f * sigm(E3 + O3));
            size_t o0i = ((size_t)(row0 + c0)     * T_ + (T_ - 1)) * A_ + gid;
            size_t o1i = ((size_t)(row0 + c0 + 1) * T_ + (T_ - 1)) * A_ + gid;
            out[o0i] = s0; out[o1i] = s1; out[o0i + 8] = s2; out[o1i + 8] = s3;
            out_o[(size_t)(row0 + c0)     * A_ + gid]     = s0;
            out_o[(size_t)(row0 + c0 + 1) * A_ + gid]     = s1;
            out_o[(size_t)(row0 + c0)     * A_ + gid + 8] = s2;
            out_o[(size_t)(row0 + c0 + 1) * A_ + gid + 8] = s3;
        }
    }
}

extern "C" void kernel_launch(void* const* d_in, const int* in_sizes, int n_in,
                              void* d_out, int out_size)
{
    (void)in_sizes; (void)n_in; (void)out_size;
    rnn_hmma3_kernel<<<NBLK, NTH>>>(
        (const float*)d_in[0],   // obs
        (const float*)d_in[1],   // W_in
        (const float*)d_in[2],   // W_h
        (const float*)d_in[3],   // b_h
        (const float*)d_in[4],   // W_out
        (const float*)d_in[5],   // b_out
        (float*)d_out);
}

// round 9
// speedup vs baseline: 1.4112x; 1.4112x over previous
#include <cuda_runtime.h>
#include <cuda_fp16.h>
#include <cstdint>

#define B_    1024
#define T_    512
#define OBS_  64
#define H_    256
#define A_    16
#define NCOL  8               // batch columns per CTA
#define NBLK  (B_ / NCOL)     // 128 CTAs
#define NTH   544             // 16 compute warps (1 m16-tile each) + 1 output warp
#define XBUF  4096            // bytes per h buffer (256 rows x 8 cols fp16)

// xp scratch: [t][cta][warp][lane] -> uint2 = 4 halfs in C-fragment order
__device__ uint2 g_xp[(size_t)T_ * NBLK * 16 * 32];

__device__ __forceinline__ float sigm(float x) {           // accurate: EX2 + RCP
    float e, r;
    asm("ex2.approx.f32 %0, %1;" : "=f"(e) : "f"(-1.4426950408889634f * x));
    asm("rcp.approx.f32 %0, %1;" : "=f"(r) : "f"(1.0f + e));
    return r;
}
__device__ __forceinline__ float tanh_(float x) {
    float t;
    asm("tanh.approx.f32 %0, %1;" : "=f"(t) : "f"(x));
    return t;
}
__device__ __forceinline__ uint32_t f2h2(float x, float y) {
    __half2 h = __floats2half2_rn(x, y);
    return *(uint32_t*)&h;
}
__device__ __forceinline__ void sts16(uint32_t a, float v) {
    uint16_t u = __half_as_ushort(__float2half_rn(v));
    asm volatile("st.shared.u16 [%0], %1;" :: "r"(a), "h"(u) : "memory");
}
__device__ __forceinline__ void ldfrag(uint32_t* f, const float* p0, const float* p1) {
    float2 a = *(const float2*)p0,       b = *(const float2*)p1;
    float2 c = *(const float2*)(p0 + 8), d = *(const float2*)(p1 + 8);
    f[0] = f2h2(a.x, a.y); f[1] = f2h2(b.x, b.y);
    f[2] = f2h2(c.x, c.y); f[3] = f2h2(d.x, d.y);
}
#define MMA(d0,d1,d2,d3,a,b0,b1) \
    asm("mma.sync.aligned.m16n8k16.row.col.f32.f16.f16.f32 " \
        "{%0,%1,%2,%3},{%4,%5,%6,%7},{%8,%9},{%0,%1,%2,%3};" \
        : "+f"(d0), "+f"(d1), "+f"(d2), "+f"(d3) \
        : "r"((a)[0]), "r"((a)[1]), "r"((a)[2]), "r"((a)[3]), "r"(b0), "r"(b1))
#define LDSV2(b0,b1,addr) \
    asm volatile("ld.shared.v2.b32 {%0,%1}, [%2];" : "=r"(b0), "=r"(b1) : "r"(addr))

// ===================== kernel 1: xp = W_in @ obs + b_h (all t) =====================
// grid (128 c, 8 tc), block 512 (16 warps). Output fp16 in C-frag order.
__global__ void __launch_bounds__(512, 2)
xproj_kernel(const float* __restrict__ obs, const float* __restrict__ W_in,
             const float* __restrict__ b_h)
{
    const int c   = blockIdx.x;
    const int tc  = blockIdx.y;
    const int tid = threadIdx.x;
    const int w   = tid >> 5;
    const int gid = (tid & 31) >> 2;
    const int tig = tid & 3;
    const int lane = tid & 31;
    const int j0  = w * 16 + gid;
    const int b   = c * 8 + gid;               // batch col = gid (B-frag n = gid)

    uint32_t af[4][4];
    #pragma unroll
    for (int kc = 0; kc < 4; kc++)
        ldfrag(af[kc], W_in + j0 * OBS_ + kc * 16 + tig * 2,
                       W_in + (j0 + 8) * OBS_ + kc * 16 + tig * 2);
    const float bh0 = b_h[j0], bh1 = b_h[j0 + 8];

    const float2* ob2 = (const float2*)obs;
    #pragma unroll 2
    for (int tt = 0; tt < 64; tt++) {
        const int t = tc * 64 + tt;
        const size_t base = ((size_t)b * T_ + t) * 32;   // float2 index
        float A0 = bh0, A1 = bh0, A2 = bh1, A3 = bh1;
        #pragma unroll
        for (int kc = 0; kc < 4; kc++) {
            // B-frag: b0 = obs[k=16kc+2tig .. +1], b1 = +8, col = gid
            float2 x0 = ob2[base + kc * 8 + tig];
            float2 x1 = ob2[base + kc * 8 + tig + 4];
            uint32_t b0 = f2h2(x0.x, x0.y), b1 = f2h2(x1.x, x1.y);
            MMA(A0, A1, A2, A3, af[kc], b0, b1);
        }
        uint2 v; v.x = f2h2(A0, A1); v.y = f2h2(A2, A3);
        g_xp[(((size_t)t * NBLK + c) * 16 + w) * 32 + lane] = v;
    }
}

// ===================== kernel 2: persistent recurrence =====================
// h layout per buffer (u32 words): word(j,n) = ((j>>4)*4 + ((j&7)>>1))*16 + 2n + ((j>>3)&1),
// halfword j&1. B-frag of thread (tig,gid) for chunk kc = ld.shared.v2.b32
// at xbase + (tig*8+gid)*8 + kc*256.
__global__ void __launch_bounds__(NTH, 1)
rnn_step_kernel(const float* __restrict__ W_h, const float* __restrict__ W_out,
                const float* __restrict__ b_out, float* __restrict__ out)
{
    __shared__ __align__(16) uint32_t xS[2 * 1024];

    const int tid  = threadIdx.x;
    const int wid  = tid >> 5;
    const int gid  = (tid & 31) >> 2;
    const int tig  = tid & 3;
    const int lane = tid & 31;
    const int kq   = tig * 2;
    const int c    = blockIdx.x;
    const int row0 = c * NCOL;
    const uint32_t xbase = (uint32_t)__cvta_generic_to_shared(xS);
    const uint32_t baddr = xbase + (uint32_t)((tig * 8 + gid) * 8);

    float* out_h = out + (size_t)B_ * T_ * A_;
    float* out_o = out_h + (size_t)B_ * H_;

    for (int i = tid; i < 2048; i += NTH) xS[i] = 0u;
    __syncthreads();

    if (wid < 16) {
        // ============ compute warps: one m16 tile of pre_h = xp + W_h @ h ============
        const int j0 = wid * 16 + gid;
        uint32_t af[16][4];
        #pragma unroll
        for (int kc = 0; kc < 16; kc++)
            ldfrag(af[kc], W_h + j0 * H_ + kc * 16 + kq,
                           W_h + (j0 + 8) * H_ + kc * 16 + kq);

        const uint2* xp = g_xp + ((size_t)c * 16 + wid) * 32 + lane;
        const size_t XSTR = (size_t)NBLK * 16 * 32;      // per-t stride in uint2
        uint2 px = xp[0];                                 // xp(0)

        // h write-back base: rows j0/j0+8, cols 2tig/2tig+1; offsets {0,8,4,12}
        const uint32_t hA = xbase +
            (uint32_t)((wid * 4 + (gid >> 1)) * 64 + tig * 16 + (gid & 1) * 2);

        float s0 = 0.f, s1 = 0.f, s2 = 0.f, s3 = 0.f;

        for (int t = 0; t < T_; t++) {
            __syncthreads();                               // buf[t&1] holds h_{t-1}
            uint2 npx = px;
            if (t + 1 < T_) npx = xp[(size_t)(t + 1) * XSTR];
            const uint32_t xb = baddr + (uint32_t)((t & 1) * XBUF);

            float2 e01 = __half22float2(*(__half2*)&px.x);
            float2 e23 = __half22float2(*(__half2*)&px.y);
            float E0 = e01.x, E1 = e01.y, E2 = e23.x, E3 = e23.y;  // even chunks + xp
            float O0 = 0.f, O1 = 0.f, O2 = 0.f, O3 = 0.f;          // odd chunks
            #pragma unroll
            for (int kc = 0; kc < 16; kc += 2) {
                uint32_t b0, b1, c0, c1;
                LDSV2(b0, b1, xb + kc * 256);
                LDSV2(c0, c1, xb + (kc + 1) * 256);
                MMA(E0, E1, E2, E3, af[kc],     b0, b1);
                MMA(O0, O1, O2, O3, af[kc + 1], c0, c1);
            }
            s0 = fmaf(0.9f, s0, fmaf(0.05f, tanh_(0.5f * (E0 + O0)), 0.05f));
            s1 = fmaf(0.9f, s1, fmaf(0.05f, tanh_(0.5f * (E1 + O1)), 0.05f));
            s2 = fmaf(0.9f, s2, fmaf(0.05f, tanh_(0.5f * (E2 + O2)), 0.05f));
            s3 = fmaf(0.9f, s3, fmaf(0.05f, tanh_(0.5f * (E3 + O3)), 0.05f));

            const uint32_t hw = hA + (uint32_t)(((t + 1) & 1) * XBUF);
            sts16(hw,      s0); sts16(hw + 8,  s1);
            sts16(hw + 4,  s2); sts16(hw + 12, s3);
            px = npx;
        }
        __syncthreads();

        const int c0 = tig * 2;
        out_h[(size_t)(row0 + c0)     * H_ + j0]     = s0;
        out_h[(size_t)(row0 + c0 + 1) * H_ + j0]     = s1;
        out_h[(size_t)(row0 + c0)     * H_ + j0 + 8] = s2;
        out_h[(size_t)(row0 + c0 + 1) * H_ + j0 + 8] = s3;
    } else {
        // ============ output warp: pre_o = W_out @ h (one step behind) ============
        uint32_t afo[16][4];
        #pragma unroll
        for (int kc = 0; kc < 16; kc++)
            ldfrag(afo[kc], W_out + gid * H_ + kc * 16 + kq,
                            W_out + (gid + 8) * H_ + kc * 16 + kq);
        const float bo0 = b_out[gid], bo1 = b_out[gid + 8];
        float s0 = 0.f, s1 = 0.f, s2 = 0.f, s3 = 0.f;
        const int c0 = tig * 2;

        for (int t = 0; t < T_; t++) {
            __syncthreads();
            if (t > 0) {
                const uint32_t xb = baddr + (uint32_t)((t & 1) * XBUF);
                float E0 = bo0, E1 = bo0, E2 = bo1, E3 = bo1;
                float O0 = 0.f, O1 = 0.f, O2 = 0.f, O3 = 0.f;
                #pragma unroll
                for (int kc = 0; kc < 16; kc += 2) {
                    uint32_t b0, b1, c1, c2;
                    LDSV2(b0, b1, xb + kc * 256);
                    LDSV2(c1, c2, xb + (kc + 1) * 256);
                    MMA(E0, E1, E2, E3, afo[kc], b0, b1);
                    MMA(O0, O1, O2, O3, afo[kc + 1], c1, c2);
                }
                s0 = fmaf(0.9f, s0, 0.1f * sigm(E0 + O0));
                s1 = fmaf(0.9f, s1, 0.1f * sigm(E1 + O1));
                s2 = fmaf(0.9f, s2, 0.1f * sigm(E2 + O2));
                s3 = fmaf(0.9f, s3, 0.1f * sigm(E3 + O3));
                size_t o0i = ((size_t)(row0 + c0)     * T_ + (t - 1)) * A_ + gid;
                size_t o1i = ((size_t)(row0 + c0 + 1) * T_ + (t - 1)) * A_ + gid;
                out[o0i] = s0; out[o1i] = s1; out[o0i + 8] = s2; out[o1i + 8] = s3;
            }
        }
        __syncthreads();

        // final pass: consume h_{T-1} from buf[T&1] == buf0
        {
            const uint32_t xb = baddr;
            float E0 = bo0, E1 = bo0, E2 = bo1, E3 = bo1;
            float O0 = 0.f, O1 = 0.f, O2 = 0.f, O3 = 0.f;
            #pragma unroll
            for (int kc = 0; kc < 16; kc += 2) {
                uint32_t b0, b1, c1, c2;
                LDSV2(b0, b1, xb + kc * 256);
                LDSV2(c1, c2, xb + (kc + 1) * 256);
                MMA(E0, E1, E2, E3, afo[kc], b0, b1);
                MMA(O0, O1, O2, O3, afo[kc + 1], c1, c2);
            }
            s0 = fmaf(0.9f, s0, 0.1f * sigm(E0 + O0));
            s1 = fmaf(0.9f, s1, 0.1f * sigm(E1 + O1));
            s2 = fmaf(0.9f, s2, 0.1f * sigm(E2 + O2));
            s3 = fmaf(0.9f, s3, 0.1f * sigm(E3 + O3));
            size_t o0i = ((size_t)(row0 + c0)     * T_ + (T_ - 1)) * A_ + gid;
            size_t o1i = ((size_t)(row0 + c0 + 1) * T_ + (T_ - 1)) * A_ + gid;
            out[o0i] = s0; out[o1i] = s1; out[o0i + 8] = s2; out[o1i + 8] = s3;
            out_o[(size_t)(row0 + c0)     * A_ + gid]     = s0;
            out_o[(size_t)(row0 + c0 + 1) * A_ + gid]     = s1;
            out_o[(size_t)(row0 + c0)     * A_ + gid + 8] = s2;
            out_o[(size_t)(row0 + c0 + 1) * A_ + gid + 8] = s3;
        }
    }
}

extern "C" void kernel_launch(void* const* d_in, const int* in_sizes, int n_in,
                              void* d_out, int out_size)
{
    (void)in_sizes; (void)n_in; (void)out_size;
    dim3 g1(NBLK, 8);
    xproj_kernel<<<g1, 512>>>(
        (const float*)d_in[0],   // obs
        (const float*)d_in[1],   // W_in
        (const float*)d_in[3]);  // b_h
    rnn_step_kernel<<<NBLK, NTH>>>(
        (const float*)d_in[2],   // W_h
        (const float*)d_in[4],   // W_out
        (const float*)d_in[5],   // b_out
        (float*)d_out);
}

// round 10
// speedup vs baseline: 1.5883x; 1.1255x over previous
#include <cuda_runtime.h>
#include <cuda_fp16.h>
#include <cstdint>

#define B_    1024
#define T_    512
#define OBS_  64
#define H_    256
#define A_    16
#define NCOL  8               // batch columns per CTA
#define NBLK  (B_ / NCOL)     // 128 CTAs
#define NTH   544             // 16 compute warps (1 m16-tile each) + 1 output warp
#define XBUF  4096            // bytes per h buffer (256 rows x 8 cols fp16)

// xp scratch: [t][cta][warp][lane] -> uint2 = 4 halfs in C-fragment order
__device__ uint2 g_xp[(size_t)T_ * NBLK * 16 * 32];

__device__ __forceinline__ float sigm(float x) {           // accurate: EX2 + RCP
    float e, r;
    asm("ex2.approx.f32 %0, %1;" : "=f"(e) : "f"(-1.4426950408889634f * x));
    asm("rcp.approx.f32 %0, %1;" : "=f"(r) : "f"(1.0f + e));
    return r;
}
__device__ __forceinline__ float tanh_(float x) {
    float t;
    asm("tanh.approx.f32 %0, %1;" : "=f"(t) : "f"(x));
    return t;
}
__device__ __forceinline__ uint32_t f2h2(float x, float y) {
    __half2 h = __floats2half2_rn(x, y);
    return *(uint32_t*)&h;
}
__device__ __forceinline__ void sts16(uint32_t a, float v) {
    uint16_t u = __half_as_ushort(__float2half_rn(v));
    asm volatile("st.shared.u16 [%0], %1;" :: "r"(a), "h"(u) : "memory");
}
__device__ __forceinline__ void ldfrag(uint32_t* f, const float* p0, const float* p1) {
    float2 a = *(const float2*)p0,       b = *(const float2*)p1;
    float2 c = *(const float2*)(p0 + 8), d = *(const float2*)(p1 + 8);
    f[0] = f2h2(a.x, a.y); f[1] = f2h2(b.x, b.y);
    f[2] = f2h2(c.x, c.y); f[3] = f2h2(d.x, d.y);
}
#define MMA(d0,d1,d2,d3,a,b0,b1) \
    asm("mma.sync.aligned.m16n8k16.row.col.f32.f16.f16.f32 " \
        "{%0,%1,%2,%3},{%4,%5,%6,%7},{%8,%9},{%0,%1,%2,%3};" \
        : "+f"(d0), "+f"(d1), "+f"(d2), "+f"(d3) \
        : "r"((a)[0]), "r"((a)[1]), "r"((a)[2]), "r"((a)[3]), "r"(b0), "r"(b1))
#define LDSV2(b0,b1,addr) \
    asm volatile("ld.shared.v2.b32 {%0,%1}, [%2];" : "=r"(b0), "=r"(b1) : "r"(addr))

// ---- swizzled x layout (per 1KB block of [64k x 8n] or 4KB of [256k x 8n]) ----
// half (k,n) lives at word  (k>>4)*64 + ((k&7)>>1)*16 + 2*((n ^ (k&4)) & 7) + ((k>>3)&1),
// halfword k&1.  B-frag of thread (tig,gid), chunk kc = ld.shared.v2.b32 at
//   base + tig*64 + 8*((gid ^ ((tig&2)<<1)) & 7) + kc*256      (conflict-free)

// ===================== kernel 1: xp = W_in @ obs + b_h (all t) =====================
__global__ void __launch_bounds__(512, 2)
xproj2_kernel(const float* __restrict__ obs, const float* __restrict__ W_in,
              const float* __restrict__ b_h)
{
    __shared__ __align__(128) uint32_t sx[2048];   // 8 t-blocks x 256 words = 8 KB

    const int c    = blockIdx.x;
    const int tc   = blockIdx.y;
    const int tid  = threadIdx.x;
    const int w    = tid >> 5;
    const int lane = tid & 31;
    const int gid  = lane >> 2;
    const int tig  = lane & 3;
    const int j0   = w * 16 + gid;
    const int row0 = c * NCOL;
    const uint32_t xbase = (uint32_t)__cvta_generic_to_shared(sx);
    const uint32_t baddr = xbase + (uint32_t)(tig * 64 + 8 * ((gid ^ ((tig & 2) << 1)) & 7));

    uint32_t af[4][4];
    #pragma unroll
    for (int kc = 0; kc < 4; kc++)
        ldfrag(af[kc], W_in + j0 * OBS_ + kc * 16 + tig * 2,
                       W_in + (j0 + 8) * OBS_ + kc * 16 + tig * 2);
    const float bh0 = b_h[j0], bh1 = b_h[j0 + 8];

    const float4* obs4 = (const float4*)obs;

    for (int it = 0; it < 8; it++) {
        const int t0 = tc * 64 + it * 8;
        // ---- stage obs[8b x 8t x 64k] -> swizzled fp16 smem (coalesced LDG) ----
        #pragma unroll
        for (int m = 0; m < 2; m++) {
            const int idx4 = m * 512 + tid;
            const int b = idx4 >> 7, tt = (idx4 >> 4) & 7, kq4 = idx4 & 15;
            float4 v = obs4[((size_t)(row0 + b) * T_ + (t0 + tt)) * 16 + kq4];
            const int k0 = kq4 * 4;
            const int word0 = tt * 256 + (k0 >> 4) * 64 + ((k0 & 7) >> 1) * 16 +
                              2 * ((b ^ (k0 & 4)) & 7) + ((k0 >> 3) & 1);
            sx[word0]      = f2h2(v.x, v.y);
            sx[word0 + 16] = f2h2(v.z, v.w);
        }
        __syncthreads();
        // ---- compute 8 timesteps, store C-frags to g_xp (coalesced STG) ----
        #pragma unroll
        for (int tt = 0; tt < 8; tt++) {
            float A0 = bh0, A1 = bh0, A2 = bh1, A3 = bh1;
            #pragma unroll
            for (int kc = 0; kc < 4; kc++) {
                uint32_t b0, b1;
                LDSV2(b0, b1, baddr + tt * 1024 + kc * 256);
                MMA(A0, A1, A2, A3, af[kc], b0, b1);
            }
            uint2 vv; vv.x = f2h2(A0, A1); vv.y = f2h2(A2, A3);
            g_xp[(((size_t)(t0 + tt) * NBLK + c) * 16 + w) * 32 + lane] = vv;
        }
        __syncthreads();
    }
}

// ===================== kernel 2: persistent recurrence =====================
__global__ void __launch_bounds__(NTH, 1)
rnn_step_kernel(const float* __restrict__ W_h, const float* __restrict__ W_out,
                const float* __restrict__ b_out, float* __restrict__ out)
{
    __shared__ __align__(128) uint32_t xS[2 * 1024];

    const int tid  = threadIdx.x;
    const int wid  = tid >> 5;
    const int gid  = (tid & 31) >> 2;
    const int tig  = tid & 3;
    const int lane = tid & 31;
    const int kq   = tig * 2;
    const int c    = blockIdx.x;
    const int row0 = c * NCOL;
    const uint32_t xbase = (uint32_t)__cvta_generic_to_shared(xS);
    const uint32_t baddr = xbase + (uint32_t)(tig * 64 + 8 * ((gid ^ ((tig & 2) << 1)) & 7));

    float* out_h = out + (size_t)B_ * T_ * A_;
    float* out_o = out_h + (size_t)B_ * H_;

    for (int i = tid; i < 2048; i += NTH) xS[i] = 0u;
    __syncthreads();

    if (wid < 16) {
        // ============ compute warps: one m16 tile of pre_h = xp + W_h @ h ============
        const int j0 = wid * 16 + gid;
        uint32_t af[16][4];
        #pragma unroll
        for (int kc = 0; kc < 16; kc++)
            ldfrag(af[kc], W_h + j0 * H_ + kc * 16 + kq,
                           W_h + (j0 + 8) * H_ + kc * 16 + kq);

        const uint2* xp = g_xp + ((size_t)c * 16 + wid) * 32 + lane;
        const size_t XSTR = (size_t)NBLK * 16 * 32;      // per-t stride in uint2
        uint2 px = xp[0];                                 // xp(0)

        // h write-back base (swizzled): rows j0/j0+8, cols 2tig/2tig+1
        const uint32_t hA = xbase +
            (uint32_t)(4 * (wid * 64 + (gid >> 1) * 16) + (gid & 1) * 2 +
                       8 * ((2 * tig ^ (gid & 4)) & 7));

        float s0 = 0.f, s1 = 0.f, s2 = 0.f, s3 = 0.f;

        for (int t = 0; t < T_; t++) {
            __syncthreads();                               // buf[t&1] holds h_{t-1}
            uint2 npx = px;
            if (t + 1 < T_) npx = xp[(size_t)(t + 1) * XSTR];
            const uint32_t xb = baddr + (uint32_t)((t & 1) * XBUF);

            float2 e01 = __half22float2(*(__half2*)&px.x);
            float2 e23 = __half22float2(*(__half2*)&px.y);
            float E0 = e01.x, E1 = e01.y, E2 = e23.x, E3 = e23.y;  // even chunks + xp
            float O0 = 0.f, O1 = 0.f, O2 = 0.f, O3 = 0.f;          // odd chunks
            #pragma unroll
            for (int kc = 0; kc < 16; kc += 2) {
                uint32_t b0, b1, c0, c1;
                LDSV2(b0, b1, xb + kc * 256);
                LDSV2(c0, c1, xb + (kc + 1) * 256);
                MMA(E0, E1, E2, E3, af[kc],     b0, b1);
                MMA(O0, O1, O2, O3, af[kc + 1], c0, c1);
            }
            s0 = fmaf(0.9f, s0, fmaf(0.05f, tanh_(0.5f * (E0 + O0)), 0.05f));
            s1 = fmaf(0.9f, s1, fmaf(0.05f, tanh_(0.5f * (E1 + O1)), 0.05f));
            s2 = fmaf(0.9f, s2, fmaf(0.05f, tanh_(0.5f * (E2 + O2)), 0.05f));
            s3 = fmaf(0.9f, s3, fmaf(0.05f, tanh_(0.5f * (E3 + O3)), 0.05f));

            const uint32_t hw = hA + (uint32_t)(((t + 1) & 1) * XBUF);
            sts16(hw,      s0); sts16(hw + 8,  s1);
            sts16(hw + 4,  s2); sts16(hw + 12, s3);
            px = npx;
        }
        __syncthreads();

        const int c0 = tig * 2;
        out_h[(size_t)(row0 + c0)     * H_ + j0]     = s0;
        out_h[(size_t)(row0 + c0 + 1) * H_ + j0]     = s1;
        out_h[(size_t)(row0 + c0)     * H_ + j0 + 8] = s2;
        out_h[(size_t)(row0 + c0 + 1) * H_ + j0 + 8] = s3;
    } else {
        // ============ output warp: pre_o = W_out @ h (one step behind) ============
        uint32_t afo[16][4];
        #pragma unroll
        for (int kc = 0; kc < 16; kc++)
            ldfrag(afo[kc], W_out + gid * H_ + kc * 16 + kq,
                            W_out + (gid + 8) * H_ + kc * 16 + kq);
        const float bo0 = b_out[gid], bo1 = b_out[gid + 8];
        float s0 = 0.f, s1 = 0.f, s2 = 0.f, s3 = 0.f;
        const int c0 = tig * 2;

        for (int t = 0; t < T_; t++) {
            __syncthreads();
            if (t > 0) {
                const uint32_t xb = baddr + (uint32_t)((t & 1) * XBUF);
                float E0 = bo0, E1 = bo0, E2 = bo1, E3 = bo1;
                float O0 = 0.f, O1 = 0.f, O2 = 0.f, O3 = 0.f;
                #pragma unroll
                for (int kc = 0; kc < 16; kc += 2) {
                    uint32_t b0, b1, c1, c2;
                    LDSV2(b0, b1, xb + kc * 256);
                    LDSV2(c1, c2, xb + (kc + 1) * 256);
                    MMA(E0, E1, E2, E3, afo[kc], b0, b1);
                    MMA(O0, O1, O2, O3, afo[kc + 1], c1, c2);
                }
                s0 = fmaf(0.9f, s0, 0.1f * sigm(E0 + O0));
                s1 = fmaf(0.9f, s1, 0.1f * sigm(E1 + O1));
                s2 = fmaf(0.9f, s2, 0.1f * sigm(E2 + O2));
                s3 = fmaf(0.9f, s3, 0.1f * sigm(E3 + O3));
                size_t o0i = ((size_t)(row0 + c0)     * T_ + (t - 1)) * A_ + gid;
                size_t o1i = ((size_t)(row0 + c0 + 1) * T_ + (t - 1)) * A_ + gid;
                out[o0i] = s0; out[o1i] = s1; out[o0i + 8] = s2; out[o1i + 8] = s3;
            }
        }
        __syncthreads();

        // final pass: consume h_{T-1} from buf[T&1] == buf0
        {
            const uint32_t xb = baddr;
            float E0 = bo0, E1 = bo0, E2 = bo1, E3 = bo1;
            float O0 = 0.f, O1 = 0.f, O2 = 0.f, O3 = 0.f;
            #pragma unroll
            for (int kc = 0; kc < 16; kc += 2) {
                uint32_t b0, b1, c1, c2;
                LDSV2(b0, b1, xb + kc * 256);
                LDSV2(c1, c2, xb + (kc + 1) * 256);
                MMA(E0, E1, E2, E3, afo[kc], b0, b1);
                MMA(O0, O1, O2, O3, afo[kc + 1], c1, c2);
            }
            s0 = fmaf(0.9f, s0, 0.1f * sigm(E0 + O0));
            s1 = fmaf(0.9f, s1, 0.1f * sigm(E1 + O1));
            s2 = fmaf(0.9f, s2, 0.1f * sigm(E2 + O2));
            s3 = fmaf(0.9f, s3, 0.1f * sigm(E3 + O3));
            size_t o0i = ((size_t)(row0 + c0)     * T_ + (T_ - 1)) * A_ + gid;
            size_t o1i = ((size_t)(row0 + c0 + 1) * T_ + (T_ - 1)) * A_ + gid;
            out[o0i] = s0; out[o1i] = s1; out[o0i + 8] = s2; out[o1i + 8] = s3;
            out_o[(size_t)(row0 + c0)     * A_ + gid]     = s0;
            out_o[(size_t)(row0 + c0 + 1) * A_ + gid]     = s1;
            out_o[(size_t)(row0 + c0)     * A_ + gid + 8] = s2;
            out_o[(size_t)(row0 + c0 + 1) * A_ + gid + 8] = s3;
        }
    }
}

extern "C" void kernel_launch(void* const* d_in, const int* in_sizes, int n_in,
                              void* d_out, int out_size)
{
    (void)in_sizes; (void)n_in; (void)out_size;
    dim3 g1(NBLK, 8);
    xproj2_kernel<<<g1, 512>>>(
        (const float*)d_in[0],   // obs
        (const float*)d_in[1],   // W_in
        (const float*)d_in[3]);  // b_h
    rnn_step_kernel<<<NBLK, NTH>>>(
        (const float*)d_in[2],   // W_h
        (const float*)d_in[4],   // W_out
        (const float*)d_in[5],   // b_out
        (float*)d_out);
}

// round 11
// speedup vs baseline: 1.8636x; 1.1733x over previous
#include <cuda_runtime.h>
#include <cuda_fp16.h>
#include <cstdint>

#define B_    1024
#define T_    512
#define OBS_  64
#define H_    256
#define A_    16
#define NCOL  8               // batch columns per CTA
#define NBLK  (B_ / NCOL)     // 128 CTAs
#define NTH   288             // 8 compute warps (2 m16-tiles each) + 1 output warp
#define XBUF  4096            // bytes per h buffer (256 rows x 8 cols fp16)

// xp scratch: [t][cta][tile16][lane] -> uint2 = 4 halfs in C-fragment order
__device__ uint2 g_xp[(size_t)T_ * NBLK * 16 * 32];

__device__ __forceinline__ float sigm(float x) {           // accurate: EX2 + RCP
    float e, r;
    asm("ex2.approx.f32 %0, %1;" : "=f"(e) : "f"(-1.4426950408889634f * x));
    asm("rcp.approx.f32 %0, %1;" : "=f"(r) : "f"(1.0f + e));
    return r;
}
__device__ __forceinline__ float tanh_(float x) {
    float t;
    asm("tanh.approx.f32 %0, %1;" : "=f"(t) : "f"(x));
    return t;
}
__device__ __forceinline__ uint32_t f2h2(float x, float y) {
    __half2 h = __floats2half2_rn(x, y);
    return *(uint32_t*)&h;
}
__device__ __forceinline__ void sts16(uint32_t a, float v) {
    uint16_t u = __half_as_ushort(__float2half_rn(v));
    asm volatile("st.shared.u16 [%0], %1;" :: "r"(a), "h"(u) : "memory");
}
__device__ __forceinline__ void ldfrag(uint32_t* f, const float* p0, const float* p1) {
    float2 a = *(const float2*)p0,       b = *(const float2*)p1;
    float2 c = *(const float2*)(p0 + 8), d = *(const float2*)(p1 + 8);
    f[0] = f2h2(a.x, a.y); f[1] = f2h2(b.x, b.y);
    f[2] = f2h2(c.x, c.y); f[3] = f2h2(d.x, d.y);
}
#define MMA(d0,d1,d2,d3,a,b0,b1) \
    asm("mma.sync.aligned.m16n8k16.row.col.f32.f16.f16.f32 " \
        "{%0,%1,%2,%3},{%4,%5,%6,%7},{%8,%9},{%0,%1,%2,%3};" \
        : "+f"(d0), "+f"(d1), "+f"(d2), "+f"(d3) \
        : "r"((a)[0]), "r"((a)[1]), "r"((a)[2]), "r"((a)[3]), "r"(b0), "r"(b1))
#define LDSV2(b0,b1,addr) \
    asm volatile("ld.shared.v2.b32 {%0,%1}, [%2];" : "=r"(b0), "=r"(b1) : "r"(addr))

// ---- swizzled x layout (per 4KB buffer of [256k x 8n] fp16) ----
// half (k,n) at word (k>>4)*64 + ((k&7)>>1)*16 + 2*((n ^ (k&4)) & 7) + ((k>>3)&1),
// halfword k&1.  B-frag of thread (tig,gid), chunk kc = ld.shared.v2.b32 at
//   base + tig*64 + 8*((gid ^ ((tig&2)<<1)) & 7) + kc*256      (conflict-free)

// ===================== kernel 1: xp = W_in @ obs + b_h (all t) =====================
__global__ void __launch_bounds__(512, 2)
xproj2_kernel(const float* __restrict__ obs, const float* __restrict__ W_in,
              const float* __restrict__ b_h)
{
    __shared__ __align__(128) uint32_t sx[2048];   // 8 t-blocks x 256 words = 8 KB

    const int c    = blockIdx.x;
    const int tc   = blockIdx.y;
    const int tid  = threadIdx.x;
    const int w    = tid >> 5;
    const int lane = tid & 31;
    const int gid  = lane >> 2;
    const int tig  = lane & 3;
    const int j0   = w * 16 + gid;
    const int row0 = c * NCOL;
    const uint32_t xbase = (uint32_t)__cvta_generic_to_shared(sx);
    const uint32_t baddr = xbase + (uint32_t)(tig * 64 + 8 * ((gid ^ ((tig & 2) << 1)) & 7));

    uint32_t af[4][4];
    #pragma unroll
    for (int kc = 0; kc < 4; kc++)
        ldfrag(af[kc], W_in + j0 * OBS_ + kc * 16 + tig * 2,
                       W_in + (j0 + 8) * OBS_ + kc * 16 + tig * 2);
    const float bh0 = b_h[j0], bh1 = b_h[j0 + 8];

    const float4* obs4 = (const float4*)obs;

    for (int it = 0; it < 8; it++) {
        const int t0 = tc * 64 + it * 8;
        // ---- stage obs[8b x 8t x 64k] -> swizzled fp16 smem (coalesced LDG) ----
        #pragma unroll
        for (int m = 0; m < 2; m++) {
            const int idx4 = m * 512 + tid;
            const int b = idx4 >> 7, tt = (idx4 >> 4) & 7, kq4 = idx4 & 15;
            float4 v = obs4[((size_t)(row0 + b) * T_ + (t0 + tt)) * 16 + kq4];
            const int k0 = kq4 * 4;
            const int word0 = tt * 256 + (k0 >> 4) * 64 + ((k0 & 7) >> 1) * 16 +
                              2 * ((b ^ (k0 & 4)) & 7) + ((k0 >> 3) & 1);
            sx[word0]      = f2h2(v.x, v.y);
            sx[word0 + 16] = f2h2(v.z, v.w);
        }
        __syncthreads();
        // ---- compute 8 timesteps, store C-frags to g_xp (coalesced STG) ----
        #pragma unroll
        for (int tt = 0; tt < 8; tt++) {
            float A0 = bh0, A1 = bh0, A2 = bh1, A3 = bh1;
            #pragma unroll
            for (int kc = 0; kc < 4; kc++) {
                uint32_t b0, b1;
                LDSV2(b0, b1, baddr + tt * 1024 + kc * 256);
                MMA(A0, A1, A2, A3, af[kc], b0, b1);
            }
            uint2 vv; vv.x = f2h2(A0, A1); vv.y = f2h2(A2, A3);
            g_xp[(((size_t)(t0 + tt) * NBLK + c) * 16 + w) * 32 + lane] = vv;
        }
        __syncthreads();
    }
}

// ===================== kernel 2: persistent recurrence =====================
__global__ void __launch_bounds__(NTH, 1)
rnn_step_kernel(const float* __restrict__ W_h, const float* __restrict__ W_out,
                const float* __restrict__ b_out, float* __restrict__ out)
{
    __shared__ __align__(128) uint32_t xS[2 * 1024];

    const int tid  = threadIdx.x;
    const int wid  = tid >> 5;
    const int gid  = (tid & 31) >> 2;
    const int tig  = tid & 3;
    const int lane = tid & 31;
    const int kq   = tig * 2;
    const int c    = blockIdx.x;
    const int row0 = c * NCOL;
    const uint32_t xbase = (uint32_t)__cvta_generic_to_shared(xS);
    const uint32_t baddr = xbase + (uint32_t)(tig * 64 + 8 * ((gid ^ ((tig & 2) << 1)) & 7));

    float* out_h = out + (size_t)B_ * T_ * A_;
    float* out_o = out_h + (size_t)B_ * H_;

    for (int i = tid; i < 2048; i += NTH) xS[i] = 0u;
    __syncthreads();

    if (wid < 8) {
        // ======= compute warps: TWO m16 tiles of pre_h = xp + W_h @ h =======
        const int tl0 = wid * 2;                 // tiles tl0, tl0+1
        const int jA  = tl0 * 16 + gid;          // tile0 row
        const int jB  = jA + 16;                 // tile1 row
        uint32_t af[2][16][4];
        #pragma unroll
        for (int kc = 0; kc < 16; kc++) {
            ldfrag(af[0][kc], W_h + jA * H_ + kc * 16 + kq,
                              W_h + (jA + 8) * H_ + kc * 16 + kq);
            ldfrag(af[1][kc], W_h + jB * H_ + kc * 16 + kq,
                              W_h + (jB + 8) * H_ + kc * 16 + kq);
        }

        const uint2* xp0 = g_xp + ((size_t)c * 16 + tl0) * 32 + lane;
        const size_t XSTR = (size_t)NBLK * 16 * 32;      // per-t stride in uint2
        uint2 px0 = xp0[0], px1 = xp0[32];               // xp(0) tiles 0,1

        // h write-back bases per tile (swizzled layout)
        const uint32_t hw_c = (uint32_t)(64 * (gid >> 1) + (gid & 1) * 2 +
                                         8 * ((2 * tig ^ (gid & 4)) & 7));
        const uint32_t hA0 = xbase + (uint32_t)(tl0 * 256) + hw_c;
        const uint32_t hA1 = hA0 + 256;

        float s00 = 0.f, s01 = 0.f, s02 = 0.f, s03 = 0.f;
        float s10 = 0.f, s11 = 0.f, s12 = 0.f, s13 = 0.f;

        for (int t = 0; t < T_; t++) {
            __syncthreads();                               // buf[t&1] holds h_{t-1}
            uint2 np0 = px0, np1 = px1;
            if (t + 1 < T_) {
                np0 = xp0[(size_t)(t + 1) * XSTR];
                np1 = xp0[(size_t)(t + 1) * XSTR + 32];
            }
            const uint32_t xb = baddr + (uint32_t)((t & 1) * XBUF);

            float2 e01 = __half22float2(*(__half2*)&px0.x);
            float2 e23 = __half22float2(*(__half2*)&px0.y);
            float2 f01 = __half22float2(*(__half2*)&px1.x);
            float2 f23 = __half22float2(*(__half2*)&px1.y);
            float E0 = e01.x, E1 = e01.y, E2 = e23.x, E3 = e23.y;  // tile0 even + xp
            float O0 = 0.f, O1 = 0.f, O2 = 0.f, O3 = 0.f;          // tile0 odd
            float F0 = f01.x, F1 = f01.y, F2 = f23.x, F3 = f23.y;  // tile1 even + xp
            float G0 = 0.f, G1 = 0.f, G2 = 0.f, G3 = 0.f;          // tile1 odd
            #pragma unroll
            for (int kc = 0; kc < 16; kc += 2) {
                uint32_t b0, b1, c0, c1;
                LDSV2(b0, b1, xb + kc * 256);
                LDSV2(c0, c1, xb + (kc + 1) * 256);
                MMA(E0, E1, E2, E3, af[0][kc],     b0, b1);
                MMA(F0, F1, F2, F3, af[1][kc],     b0, b1);
                MMA(O0, O1, O2, O3, af[0][kc + 1], c0, c1);
                MMA(G0, G1, G2, G3, af[1][kc + 1], c0, c1);
            }
            s00 = fmaf(0.9f, s00, fmaf(0.05f, tanh_(0.5f * (E0 + O0)), 0.05f));
            s01 = fmaf(0.9f, s01, fmaf(0.05f, tanh_(0.5f * (E1 + O1)), 0.05f));
            s02 = fmaf(0.9f, s02, fmaf(0.05f, tanh_(0.5f * (E2 + O2)), 0.05f));
            s03 = fmaf(0.9f, s03, fmaf(0.05f, tanh_(0.5f * (E3 + O3)), 0.05f));
            s10 = fmaf(0.9f, s10, fmaf(0.05f, tanh_(0.5f * (F0 + G0)), 0.05f));
            s11 = fmaf(0.9f, s11, fmaf(0.05f, tanh_(0.5f * (F1 + G1)), 0.05f));
            s12 = fmaf(0.9f, s12, fmaf(0.05f, tanh_(0.5f * (F2 + G2)), 0.05f));
            s13 = fmaf(0.9f, s13, fmaf(0.05f, tanh_(0.5f * (F3 + G3)), 0.05f));

            const uint32_t bo = (uint32_t)(((t + 1) & 1) * XBUF);
            sts16(hA0 + bo,      s00); sts16(hA0 + bo + 8,  s01);
            sts16(hA0 + bo + 4,  s02); sts16(hA0 + bo + 12, s03);
            sts16(hA1 + bo,      s10); sts16(hA1 + bo + 8,  s11);
            sts16(hA1 + bo + 4,  s12); sts16(hA1 + bo + 12, s13);
            px0 = np0; px1 = np1;
        }
        __syncthreads();

        const int c0 = tig * 2;
        out_h[(size_t)(row0 + c0)     * H_ + jA]     = s00;
        out_h[(size_t)(row0 + c0 + 1) * H_ + jA]     = s01;
        out_h[(size_t)(row0 + c0)     * H_ + jA + 8] = s02;
        out_h[(size_t)(row0 + c0 + 1) * H_ + jA + 8] = s03;
        out_h[(size_t)(row0 + c0)     * H_ + jB]     = s10;
        out_h[(size_t)(row0 + c0 + 1) * H_ + jB]     = s11;
        out_h[(size_t)(row0 + c0)     * H_ + jB + 8] = s12;
        out_h[(size_t)(row0 + c0 + 1) * H_ + jB + 8] = s13;
    } else {
        // ============ output warp: pre_o = W_out @ h (one step behind) ============
        uint32_t afo[16][4];
        #pragma unroll
        for (int kc = 0; kc < 16; kc++)
            ldfrag(afo[kc], W_out + gid * H_ + kc * 16 + kq,
                            W_out + (gid + 8) * H_ + kc * 16 + kq);
        const float bo0 = b_out[gid], bo1 = b_out[gid + 8];
        float s0 = 0.f, s1 = 0.f, s2 = 0.f, s3 = 0.f;
        const int c0 = tig * 2;

        for (int t = 0; t < T_; t++) {
            __syncthreads();
            if (t > 0) {
                const uint32_t xb = baddr + (uint32_t)((t & 1) * XBUF);
                float E0 = bo0, E1 = bo0, E2 = bo1, E3 = bo1;
                float O0 = 0.f, O1 = 0.f, O2 = 0.f, O3 = 0.f;
                #pragma unroll
                for (int kc = 0; kc < 16; kc += 2) {
                    uint32_t b0, b1, c1, c2;
                    LDSV2(b0, b1, xb + kc * 256);
                    LDSV2(c1, c2, xb + (kc + 1) * 256);
                    MMA(E0, E1, E2, E3, afo[kc], b0, b1);
                    MMA(O0, O1, O2, O3, afo[kc + 1], c1, c2);
                }
                s0 = fmaf(0.9f, s0, 0.1f * sigm(E0 + O0));
                s1 = fmaf(0.9f, s1, 0.1f * sigm(E1 + O1));
                s2 = fmaf(0.9f, s2, 0.1f * sigm(E2 + O2));
                s3 = fmaf(0.9f, s3, 0.1f * sigm(E3 + O3));
                size_t o0i = ((size_t)(row0 + c0)     * T_ + (t - 1)) * A_ + gid;
                size_t o1i = ((size_t)(row0 + c0 + 1) * T_ + (t - 1)) * A_ + gid;
                out[o0i] = s0; out[o1i] = s1; out[o0i + 8] = s2; out[o1i + 8] = s3;
            }
        }
        __syncthreads();

        // final pass: consume h_{T-1} from buf[T&1] == buf0
        {
            const uint32_t xb = baddr;
            float E0 = bo0, E1 = bo0, E2 = bo1, E3 = bo1;
            float O0 = 0.f, O1 = 0.f, O2 = 0.f, O3 = 0.f;
            #pragma unroll
            for (int kc = 0; kc < 16; kc += 2) {
                uint32_t b0, b1, c1, c2;
                LDSV2(b0, b1, xb + kc * 256);
                LDSV2(c1, c2, xb + (kc + 1) * 256);
                MMA(E0, E1, E2, E3, afo[kc], b0, b1);
                MMA(O0, O1, O2, O3, afo[kc + 1], c1, c2);
            }
            s0 = fmaf(0.9f, s0, 0.1f * sigm(E0 + O0));
            s1 = fmaf(0.9f, s1, 0.1f * sigm(E1 + O1));
            s2 = fmaf(0.9f, s2, 0.1f * sigm(E2 + O2));
            s3 = fmaf(0.9f, s3, 0.1f * sigm(E3 + O3));
            size_t o0i = ((size_t)(row0 + c0)     * T_ + (T_ - 1)) * A_ + gid;
            size_t o1i = ((size_t)(row0 + c0 + 1) * T_ + (T_ - 1)) * A_ + gid;
            out[o0i] = s0; out[o1i] = s1; out[o0i + 8] = s2; out[o1i + 8] = s3;
            out_o[(size_t)(row0 + c0)     * A_ + gid]     = s0;
            out_o[(size_t)(row0 + c0 + 1) * A_ + gid]     = s1;
            out_o[(size_t)(row0 + c0)     * A_ + gid + 8] = s2;
            out_o[(size_t)(row0 + c0 + 1) * A_ + gid + 8] = s3;
        }
    }
}

extern "C" void kernel_launch(void* const* d_in, const int* in_sizes, int n_in,
                              void* d_out, int out_size)
{
    (void)in_sizes; (void)n_in; (void)out_size;
    dim3 g1(NBLK, 8);
    xproj2_kernel<<<g1, 512>>>(
        (const float*)d_in[0],   // obs
        (const float*)d_in[1],   // W_in
        (const float*)d_in[3]);  // b_h
    rnn_step_kernel<<<NBLK, NTH>>>(
        (const float*)d_in[2],   // W_h
        (const float*)d_in[4],   // W_out
        (const float*)d_in[5],   // b_out
        (float*)d_out);
}

// round 14
// speedup vs baseline: 2.1521x; 1.1548x over previous
#include <cuda_runtime.h>
#include <cuda_fp16.h>
#include <cstdint>

#define B_    1024
#define T_    512
#define OBS_  64
#define H_    256
#define A_    16
#define NCOL  8               // batch columns per CTA
#define NBLK  (B_ / NCOL)     // 128 CTAs
#define NTH   288             // 8 compute warps (2 m16-tiles each) + 1 output warp
#define XBUF  4096            // bytes per h buffer (256 rows x 8 cols fp16)

// xp scratch: [t][cta][tile16][lane] -> uint2 = 4 halfs in C-fragment order
__device__ uint2 g_xp[(size_t)T_ * NBLK * 16 * 32];

__device__ __forceinline__ float sigm(float x) {           // accurate: EX2 + RCP
    float e, r;
    asm("ex2.approx.f32 %0, %1;" : "=f"(e) : "f"(-1.4426950408889634f * x));
    asm("rcp.approx.f32 %0, %1;" : "=f"(r) : "f"(1.0f + e));
    return r;
}
__device__ __forceinline__ float tanh_(float x) {
    float t;
    asm("tanh.approx.f32 %0, %1;" : "=f"(t) : "f"(x));
    return t;
}
__device__ __forceinline__ uint32_t f2h2(float x, float y) {
    __half2 h = __floats2half2_rn(x, y);
    return *(uint32_t*)&h;
}
__device__ __forceinline__ void ldfrag(uint32_t* f, const float* p0, const float* p1) {
    float2 a = *(const float2*)p0,       b = *(const float2*)p1;
    float2 c = *(const float2*)(p0 + 8), d = *(const float2*)(p1 + 8);
    f[0] = f2h2(a.x, a.y); f[1] = f2h2(b.x, b.y);
    f[2] = f2h2(c.x, c.y); f[3] = f2h2(d.x, d.y);
}
#define MMA(d0,d1,d2,d3,a,b0,b1) \
    asm("mma.sync.aligned.m16n8k16.row.col.f32.f16.f16.f32 " \
        "{%0,%1,%2,%3},{%4,%5,%6,%7},{%8,%9},{%0,%1,%2,%3};" \
        : "+f"(d0), "+f"(d1), "+f"(d2), "+f"(d3) \
        : "r"((a)[0]), "r"((a)[1]), "r"((a)[2]), "r"((a)[3]), "r"(b0), "r"(b1))
#define LDSV2(b0,b1,addr) \
    asm volatile("ld.shared.v2.b32 {%0,%1}, [%2];" : "=r"(b0), "=r"(b1) : "r"(addr))
#define STSV2(addr,b0,b1) \
    asm volatile("st.shared.v2.b32 [%0], {%1,%2};" :: "r"(addr), "r"(b0), "r"(b1) : "memory")
#define MOVM(d,s) \
    asm("movmatrix.sync.aligned.m8n8.trans.b16 %0, %1;" : "=r"(d) : "r"(s))

// ---- swizzled x layout (per 4KB buffer of [256k x 8n] fp16) ----
// half (k,n) at word (k>>4)*64 + ((k&7)>>1)*16 + 2*((n ^ (k&4)) & 7) + ((k>>3)&1),
// halfword k&1.  B-frag of thread (tig,gid), chunk kc = ld.shared.v2.b32 at
//   base + tig*64 + 8*((gid ^ ((tig&2)<<1)) & 7) + kc*256      (conflict-free)
// Writers: C-frag (rows gid/gid+8, cols 2tig/2tig+1) -> movmatrix -> the SAME
// (tig,gid) slot of chunk tl: one st.shared.v2.b32, conflict-free by construction.

// ===================== kernel 1: xp = W_in @ obs + b_h (all t) =====================
__global__ void __launch_bounds__(512, 2)
xproj2_kernel(const float* __restrict__ obs, const float* __restrict__ W_in,
              const float* __restrict__ b_h)
{
    __shared__ __align__(128) uint32_t sx[2048];   // 8 t-blocks x 256 words = 8 KB

    const int c    = blockIdx.x;
    const int tc   = blockIdx.y;
    const int tid  = threadIdx.x;
    const int w    = tid >> 5;
    const int lane = tid & 31;
    const int gid  = lane >> 2;
    const int tig  = lane & 3;
    const int j0   = w * 16 + gid;
    const int row0 = c * NCOL;
    const uint32_t xbase = (uint32_t)__cvta_generic_to_shared(sx);
    const uint32_t baddr = xbase + (uint32_t)(tig * 64 + 8 * ((gid ^ ((tig & 2) << 1)) & 7));

    uint32_t af[4][4];
    #pragma unroll
    for (int kc = 0; kc < 4; kc++)
        ldfrag(af[kc], W_in + j0 * OBS_ + kc * 16 + tig * 2,
                       W_in + (j0 + 8) * OBS_ + kc * 16 + tig * 2);
    const float bh0 = b_h[j0], bh1 = b_h[j0 + 8];

    const float4* obs4 = (const float4*)obs;

    for (int it = 0; it < 8; it++) {
        const int t0 = tc * 64 + it * 8;
        // ---- stage obs[8b x 8t x 64k] -> swizzled fp16 smem (coalesced LDG) ----
        #pragma unroll
        for (int m = 0; m < 2; m++) {
            const int idx4 = m * 512 + tid;
            const int b = idx4 >> 7, tt = (idx4 >> 4) & 7, kq4 = idx4 & 15;
            float4 v = obs4[((size_t)(row0 + b) * T_ + (t0 + tt)) * 16 + kq4];
            const int k0 = kq4 * 4;
            const int word0 = tt * 256 + (k0 >> 4) * 64 + ((k0 & 7) >> 1) * 16 +
                              2 * ((b ^ (k0 & 4)) & 7) + ((k0 >> 3) & 1);
            sx[word0]      = f2h2(v.x, v.y);
            sx[word0 + 16] = f2h2(v.z, v.w);
        }
        __syncthreads();
        // ---- compute 8 timesteps, store C-frags to g_xp (coalesced STG) ----
        #pragma unroll
        for (int tt = 0; tt < 8; tt++) {
            float A0 = bh0, A1 = bh0, A2 = bh1, A3 = bh1;
            #pragma unroll
            for (int kc = 0; kc < 4; kc++) {
                uint32_t b0, b1;
                LDSV2(b0, b1, baddr + tt * 1024 + kc * 256);
                MMA(A0, A1, A2, A3, af[kc], b0, b1);
            }
            uint2 vv; vv.x = f2h2(A0, A1); vv.y = f2h2(A2, A3);
            g_xp[(((size_t)(t0 + tt) * NBLK + c) * 16 + w) * 32 + lane] = vv;
        }
        __syncthreads();
    }
}

// ===================== kernel 2: persistent recurrence =====================
__global__ void __launch_bounds__(NTH, 1)
rnn_step_kernel(const float* __restrict__ W_h, const float* __restrict__ W_out,
                const float* __restrict__ b_out, float* __restrict__ out)
{
    __shared__ __align__(128) uint32_t xS[2 * 1024];

    const int tid  = threadIdx.x;
    const int wid  = tid >> 5;
    const int gid  = (tid & 31) >> 2;
    const int tig  = tid & 3;
    const int lane = tid & 31;
    const int kq   = tig * 2;
    const int c    = blockIdx.x;
    const int row0 = c * NCOL;
    const uint32_t xbase = (uint32_t)__cvta_generic_to_shared(xS);
    const uint32_t baddr = xbase + (uint32_t)(tig * 64 + 8 * ((gid ^ ((tig & 2) << 1)) & 7));

    float* out_h = out + (size_t)B_ * T_ * A_;
    float* out_o = out_h + (size_t)B_ * H_;

    for (int i = tid; i < 2048; i += NTH) xS[i] = 0u;
    __syncthreads();

    if (wid < 8) {
        // ======= compute warps: TWO m16 tiles of pre_h = xp + W_h @ h =======
        const int tl0 = wid * 2;                 // tiles tl0, tl0+1
        const int jA  = tl0 * 16 + gid;          // tile0 row
        const int jB  = jA + 16;                 // tile1 row
        uint32_t af[2][16][4];
        #pragma unroll
        for (int kc = 0; kc < 16; kc++) {
            ldfrag(af[0][kc], W_h + jA * H_ + kc * 16 + kq,
                              W_h + (jA + 8) * H_ + kc * 16 + kq);
            ldfrag(af[1][kc], W_h + jB * H_ + kc * 16 + kq,
                              W_h + (jB + 8) * H_ + kc * 16 + kq);
        }

        const uint2* xp0 = g_xp + ((size_t)c * 16 + tl0) * 32 + lane;
        const size_t XSTR = (size_t)NBLK * 16 * 32;      // per-t stride in uint2
        uint2 px0 = xp0[0], px1 = xp0[32];               // xp(0) tiles 0,1

        float s00 = 0.f, s01 = 0.f, s02 = 0.f, s03 = 0.f;
        float s10 = 0.f, s11 = 0.f, s12 = 0.f, s13 = 0.f;

        for (int t = 0; t < T_; t++) {
            __syncthreads();                               // buf[t&1] holds h_{t-1}
            uint2 np0 = px0, np1 = px1;
            if (t + 1 < T_) {
                np0 = xp0[(size_t)(t + 1) * XSTR];
                np1 = xp0[(size_t)(t + 1) * XSTR + 32];
            }
            const uint32_t xb = baddr + (uint32_t)((t & 1) * XBUF);

            float2 e01 = __half22float2(*(__half2*)&px0.x);
            float2 e23 = __half22float2(*(__half2*)&px0.y);
            float2 f01 = __half22float2(*(__half2*)&px1.x);
            float2 f23 = __half22float2(*(__half2*)&px1.y);
            float E0 = e01.x, E1 = e01.y, E2 = e23.x, E3 = e23.y;  // tile0 even + xp
            float O0 = 0.f, O1 = 0.f, O2 = 0.f, O3 = 0.f;          // tile0 odd
            float F0 = f01.x, F1 = f01.y, F2 = f23.x, F3 = f23.y;  // tile1 even + xp
            float G0 = 0.f, G1 = 0.f, G2 = 0.f, G3 = 0.f;          // tile1 odd
            #pragma unroll
            for (int kc = 0; kc < 16; kc += 2) {
                uint32_t b0, b1, c0, c1;
                LDSV2(b0, b1, xb + kc * 256);
                LDSV2(c0, c1, xb + (kc + 1) * 256);
                MMA(E0, E1, E2, E3, af[0][kc],     b0, b1);
                MMA(F0, F1, F2, F3, af[1][kc],     b0, b1);
                MMA(O0, O1, O2, O3, af[0][kc + 1], c0, c1);
                MMA(G0, G1, G2, G3, af[1][kc + 1], c0, c1);
            }
            s00 = fmaf(0.9f, s00, fmaf(0.05f, tanh_(0.5f * (E0 + O0)), 0.05f));
            s01 = fmaf(0.9f, s01, fmaf(0.05f, tanh_(0.5f * (E1 + O1)), 0.05f));
            s02 = fmaf(0.9f, s02, fmaf(0.05f, tanh_(0.5f * (E2 + O2)), 0.05f));
            s03 = fmaf(0.9f, s03, fmaf(0.05f, tanh_(0.5f * (E3 + O3)), 0.05f));
            s10 = fmaf(0.9f, s10, fmaf(0.05f, tanh_(0.5f * (F0 + G0)), 0.05f));
            s11 = fmaf(0.9f, s11, fmaf(0.05f, tanh_(0.5f * (F1 + G1)), 0.05f));
            s12 = fmaf(0.9f, s12, fmaf(0.05f, tanh_(0.5f * (F2 + G2)), 0.05f));
            s13 = fmaf(0.9f, s13, fmaf(0.05f, tanh_(0.5f * (F3 + G3)), 0.05f));

            // ---- h write-back: movmatrix transpose -> one conflict-free STS.64/tile ----
            {
                uint32_t u0 = f2h2(s00, s01), u1 = f2h2(s02, s03);
                uint32_t u2 = f2h2(s10, s11), u3 = f2h2(s12, s13);
                uint32_t w0, w1, w2, w3;
                MOVM(w0, u0); MOVM(w1, u1); MOVM(w2, u2); MOVM(w3, u3);
                const uint32_t wb = baddr + (uint32_t)(((t + 1) & 1) * XBUF) +
                                    (uint32_t)(tl0 * 256);
                STSV2(wb,       w0, w1);     // tile tl0  (chunk tl0 k-range)
                STSV2(wb + 256, w2, w3);     // tile tl0+1
            }
            px0 = np0; px1 = np1;
        }
        __syncthreads();

        const int c0 = tig * 2;
        out_h[(size_t)(row0 + c0)     * H_ + jA]     = s00;
        out_h[(size_t)(row0 + c0 + 1) * H_ + jA]     = s01;
        out_h[(size_t)(row0 + c0)     * H_ + jA + 8] = s02;
        out_h[(size_t)(row0 + c0 + 1) * H_ + jA + 8] = s03;
        out_h[(size_t)(row0 + c0)     * H_ + jB]     = s10;
        out_h[(size_t)(row0 + c0 + 1) * H_ + jB]     = s11;
        out_h[(size_t)(row0 + c0)     * H_ + jB + 8] = s12;
        out_h[(size_t)(row0 + c0 + 1) * H_ + jB + 8] = s13;
    } else {
        // ============ output warp: pre_o = W_out @ h (one step behind) ============
        uint32_t afo[16][4];
        #pragma unroll
        for (int kc = 0; kc < 16; kc++)
            ldfrag(afo[kc], W_out + gid * H_ + kc * 16 + kq,
                            W_out + (gid + 8) * H_ + kc * 16 + kq);
        const float bo0 = b_out[gid], bo1 = b_out[gid + 8];
        float s0 = 0.f, s1 = 0.f, s2 = 0.f, s3 = 0.f;
        const int c0 = tig * 2;

        for (int t = 0; t < T_; t++) {
            __syncthreads();
            if (t > 0) {
                const uint32_t xb = baddr + (uint32_t)((t & 1) * XBUF);
                float E0 = bo0, E1 = bo0, E2 = bo1, E3 = bo1;
                float O0 = 0.f, O1 = 0.f, O2 = 0.f, O3 = 0.f;
                #pragma unroll
                for (int kc = 0; kc < 16; kc += 2) {
                    uint32_t b0, b1, c1, c2;
                    LDSV2(b0, b1, xb + kc * 256);
                    LDSV2(c1, c2, xb + (kc + 1) * 256);
                    MMA(E0, E1, E2, E3, afo[kc], b0, b1);
                    MMA(O0, O1, O2, O3, afo[kc + 1], c1, c2);
                }
                s0 = fmaf(0.9f, s0, 0.1f * sigm(E0 + O0));
                s1 = fmaf(0.9f, s1, 0.1f * sigm(E1 + O1));
                s2 = fmaf(0.9f, s2, 0.1f * sigm(E2 + O2));
                s3 = fmaf(0.9f, s3, 0.1f * sigm(E3 + O3));
                size_t o0i = ((size_t)(row0 + c0)     * T_ + (t - 1)) * A_ + gid;
                size_t o1i = ((size_t)(row0 + c0 + 1) * T_ + (t - 1)) * A_ + gid;
                out[o0i] = s0; out[o1i] = s1; out[o0i + 8] = s2; out[o1i + 8] = s3;
            }
        }
        __syncthreads();

        // final pass: consume h_{T-1} from buf[T&1] == buf0
        {
            const uint32_t xb = baddr;
            float E0 = bo0, E1 = bo0, E2 = bo1, E3 = bo1;
            float O0 = 0.f, O1 = 0.f, O2 = 0.f, O3 = 0.f;
            #pragma unroll
            for (int kc = 0; kc < 16; kc += 2) {
                uint32_t b0, b1, c1, c2;
                LDSV2(b0, b1, xb + kc * 256);
                LDSV2(c1, c2, xb + (kc + 1) * 256);
                MMA(E0, E1, E2, E3, afo[kc], b0, b1);
                MMA(O0, O1, O2, O3, afo[kc + 1], c1, c2);
            }
            s0 = fmaf(0.9f, s0, 0.1f * sigm(E0 + O0));
            s1 = fmaf(0.9f, s1, 0.1f * sigm(E1 + O1));
            s2 = fmaf(0.9f, s2, 0.1f * sigm(E2 + O2));
            s3 = fmaf(0.9f, s3, 0.1f * sigm(E3 + O3));
            size_t o0i = ((size_t)(row0 + c0)     * T_ + (T_ - 1)) * A_ + gid;
            size_t o1i = ((size_t)(row0 + c0 + 1) * T_ + (T_ - 1)) * A_ + gid;
            out[o0i] = s0; out[o1i] = s1; out[o0i + 8] = s2; out[o1i + 8] = s3;
            out_o[(size_t)(row0 + c0)     * A_ + gid]     = s0;
            out_o[(size_t)(row0 + c0 + 1) * A_ + gid]     = s1;
            out_o[(size_t)(row0 + c0)     * A_ + gid + 8] = s2;
            out_o[(size_t)(row0 + c0 + 1) * A_ + gid + 8] = s3;
        }
    }
}

extern "C" void kernel_launch(void* const* d_in, const int* in_sizes, int n_in,
                              void* d_out, int out_size)
{
    (void)in_sizes; (void)n_in; (void)out_size;
    dim3 g1(NBLK, 8);
    xproj2_kernel<<<g1, 512>>>(
        (const float*)d_in[0],   // obs
        (const float*)d_in[1],   // W_in
        (const float*)d_in[3]);  // b_h
    rnn_step_kernel<<<NBLK, NTH>>>(
        (const float*)d_in[2],   // W_h
        (const float*)d_in[4],   // W_out
        (const float*)d_in[5],   // b_out
        (float*)d_out);
}